// round 6
// baseline (speedup 1.0000x reference)
#include <cuda_runtime.h>
#include <cuda_bf16.h>

// GraphNorm, persistent double-buffered pipeline (R6: 512 thr/CTA, occ 2x).
//   out = a*x + b,  a = gnw*rsqrt(var+eps), b = gnb - a*m*msc
//   var = E[x^2] - 2*(m*msc)*m + (m*msc)^2  (single sweep: sum x, sum x^2)
//
// Tile = (graph, 16-col chunk): 512x16 fp32 = 32 KB. Persistent CTAs
// (3/SM, 512 threads) iterate tiles; tile t+1 prefetched via cp.async.cg
// into the alternate buffer while tile t is reduced/normalized/stored.

#define TILE_D    16
#define THREADS   512
#define ROW_TILE  512
#define NWARPS    (THREADS / 32)          // 16
#define BUF_ELEMS (ROW_TILE * TILE_D)     // 8192 floats = 32 KB
#define TPR       4                       // threads per row (float4)
#define ROWSTEP   (THREADS / TPR)         // 128 rows per pass
#define NPASS     (ROW_TILE / ROWSTEP)    // 4
#define EPSV      1e-6f
#define NCTA      456                     // 3 per SM

#define SMEM_BYTES ((2*BUF_ELEMS + 2*NWARPS*TILE_D + 2*TILE_D) * sizeof(float))

__device__ __forceinline__ unsigned smem_u32(const void* p) {
    return (unsigned)__cvta_generic_to_shared(p);
}
__device__ __forceinline__ void cp16(unsigned dst, const void* src) {
    asm volatile("cp.async.cg.shared.global [%0], [%1], 16;" :: "r"(dst), "l"(src));
}
__device__ __forceinline__ void cp_commit() {
    asm volatile("cp.async.commit_group;");
}
template <int N> __device__ __forceinline__ void cp_wait() {
    asm volatile("cp.async.wait_group %0;" :: "n"(N));
}

__device__ __forceinline__ void acc4(float4 v, float4& s1, float4& s2) {
    s1.x += v.x; s1.y += v.y; s1.z += v.z; s1.w += v.w;
    s2.x = fmaf(v.x, v.x, s2.x);
    s2.y = fmaf(v.y, v.y, s2.y);
    s2.z = fmaf(v.z, v.z, s2.z);
    s2.w = fmaf(v.w, v.w, s2.w);
}

__global__ __launch_bounds__(THREADS, 3)
void graphnorm_kernel(const float* __restrict__ x,
                      const float* __restrict__ gnw,
                      const float* __restrict__ gnb,
                      const float* __restrict__ msc,
                      const int* __restrict__ bn,
                      float* __restrict__ out,
                      int D, int B)
{
    extern __shared__ float smem[];
    float* buf[2];
    buf[0] = smem;
    buf[1] = smem + BUF_ELEMS;
    float* ps1   = smem + 2 * BUF_ELEMS;       // [NWARPS][TILE_D]
    float* ps2   = ps1 + NWARPS * TILE_D;
    float* acoef = ps2 + NWARPS * TILE_D;      // [TILE_D]
    float* bcoef = acoef + TILE_D;

    const int tid  = threadIdx.x;
    const int wid  = tid >> 5;
    const int lane = tid & 31;
    const int ncc  = D / TILE_D;
    const int ntiles = B * ncc;

    const int l4   = (tid & (TPR - 1)) * 4;    // 0,4,8,12
    const int row0 = tid / TPR;                // 0..127

    int t = blockIdx.x;
    const int stride = gridDim.x;
    if (t >= ntiles) return;

    int pg = 0;
    long long pstart = 0;

    // ---- prefetch first tile ----
    int g = t / ncc;
    while (pg < g) pstart += (long long)bn[pg++];
    int cnt = bn[g];
    int cpn = min(cnt, ROW_TILE);
    const float* xg = x + pstart * (long long)D + (t % ncc) * TILE_D;
    {
        const float* p = xg + (long long)row0 * D + l4;
        unsigned d = smem_u32(buf[0] + row0 * TILE_D + l4);
        if (cpn == ROW_TILE) {
            #pragma unroll
            for (int it = 0; it < NPASS; ++it) {
                cp16(d, p);
                p += (long long)ROWSTEP * D;
                d += ROWSTEP * TILE_D * 4;
            }
        } else {
            for (int r = row0; r < cpn; r += ROWSTEP) {
                cp16(d, p);
                p += (long long)ROWSTEP * D;
                d += ROWSTEP * TILE_D * 4;
            }
        }
    }
    cp_commit();

    int bsel = 0;
    for (;;) {
        const long long cstart = pstart;
        const int   ccnt = cnt, ccpn = cpn;
        const int   cc   = t % ncc;
        const float* cxg = xg;
        float* cb = buf[bsel];

        // ---- prefetch next tile into the other buffer ----
        const int tn = t + stride;
        const bool has_next = (tn < ntiles);
        if (has_next) {
            const int gn = tn / ncc;
            while (pg < gn) pstart += (long long)bn[pg++];
            cnt = bn[gn];
            cpn = min(cnt, ROW_TILE);
            xg = x + pstart * (long long)D + (tn % ncc) * TILE_D;
            const float* p = xg + (long long)row0 * D + l4;
            unsigned d = smem_u32(buf[bsel ^ 1] + row0 * TILE_D + l4);
            if (cpn == ROW_TILE) {
                #pragma unroll
                for (int it = 0; it < NPASS; ++it) {
                    cp16(d, p);
                    p += (long long)ROWSTEP * D;
                    d += ROWSTEP * TILE_D * 4;
                }
            } else {
                for (int r = row0; r < cpn; r += ROWSTEP) {
                    cp16(d, p);
                    p += (long long)ROWSTEP * D;
                    d += ROWSTEP * TILE_D * 4;
                }
            }
            cp_commit();
            cp_wait<1>();    // current tile's loads done; next stays in flight
        } else {
            cp_wait<0>();
        }
        __syncthreads();

        // ---- reduce current tile ----
        float4 s1 = make_float4(0.f, 0.f, 0.f, 0.f);
        float4 s2 = make_float4(0.f, 0.f, 0.f, 0.f);
        if (ccpn == ROW_TILE) {
            const float* tp = cb + row0 * TILE_D + l4;
            float4 v0 = *(const float4*)(tp + 0 * ROWSTEP * TILE_D);
            float4 v1 = *(const float4*)(tp + 1 * ROWSTEP * TILE_D);
            float4 v2 = *(const float4*)(tp + 2 * ROWSTEP * TILE_D);
            float4 v3 = *(const float4*)(tp + 3 * ROWSTEP * TILE_D);
            acc4(v0, s1, s2); acc4(v1, s1, s2);
            acc4(v2, s1, s2); acc4(v3, s1, s2);
        } else {
            for (int r = row0; r < ccpn; r += ROWSTEP)
                acc4(*(const float4*)(cb + r * TILE_D + l4), s1, s2);
        }
        for (int r = ROW_TILE + row0; r < ccnt; r += ROWSTEP)
            acc4(*(const float4*)(cxg + (long long)r * D + l4), s1, s2);

        #pragma unroll
        for (int off = TPR; off < 32; off <<= 1) {
            s1.x += __shfl_xor_sync(0xffffffffu, s1.x, off);
            s1.y += __shfl_xor_sync(0xffffffffu, s1.y, off);
            s1.z += __shfl_xor_sync(0xffffffffu, s1.z, off);
            s1.w += __shfl_xor_sync(0xffffffffu, s1.w, off);
            s2.x += __shfl_xor_sync(0xffffffffu, s2.x, off);
            s2.y += __shfl_xor_sync(0xffffffffu, s2.y, off);
            s2.z += __shfl_xor_sync(0xffffffffu, s2.z, off);
            s2.w += __shfl_xor_sync(0xffffffffu, s2.w, off);
        }
        if (lane < TPR) {
            *(float4*)(ps1 + wid * TILE_D + lane * 4) = s1;
            *(float4*)(ps2 + wid * TILE_D + lane * 4) = s2;
        }
        __syncthreads();

        if (tid < TILE_D) {
            float t1 = 0.f, t2 = 0.f;
            #pragma unroll
            for (int k = 0; k < NWARPS; ++k) {
                t1 += ps1[k * TILE_D + tid];
                t2 += ps2[k * TILE_D + tid];
            }
            const float inv_n = 1.0f / (float)ccnt;
            const float m    = t1 * inv_n;
            const float ex2  = t2 * inv_n;
            const float s    = msc[cc * TILE_D + tid];
            const float ms   = m * s;
            const float var  = ex2 - 2.f * ms * m + ms * ms;
            const float rstd = rsqrtf(var + EPSV);
            const float a    = gnw[cc * TILE_D + tid] * rstd;
            acoef[tid] = a;
            bcoef[tid] = gnb[cc * TILE_D + tid] - a * ms;
        }
        __syncthreads();

        // ---- apply + store ----
        const float4 av = *(const float4*)(acoef + l4);
        const float4 bv = *(const float4*)(bcoef + l4);
        float* og = out + cstart * (long long)D + cc * TILE_D;
        if (ccpn == ROW_TILE) {
            const float* tp = cb + row0 * TILE_D + l4;
            float* q = og + (long long)row0 * D + l4;
            float4 v0 = *(const float4*)(tp + 0 * ROWSTEP * TILE_D);
            float4 v1 = *(const float4*)(tp + 1 * ROWSTEP * TILE_D);
            float4 v2 = *(const float4*)(tp + 2 * ROWSTEP * TILE_D);
            float4 v3 = *(const float4*)(tp + 3 * ROWSTEP * TILE_D);
            float4 o0, o1, o2, o3;
            o0.x = fmaf(av.x, v0.x, bv.x); o0.y = fmaf(av.y, v0.y, bv.y);
            o0.z = fmaf(av.z, v0.z, bv.z); o0.w = fmaf(av.w, v0.w, bv.w);
            o1.x = fmaf(av.x, v1.x, bv.x); o1.y = fmaf(av.y, v1.y, bv.y);
            o1.z = fmaf(av.z, v1.z, bv.z); o1.w = fmaf(av.w, v1.w, bv.w);
            o2.x = fmaf(av.x, v2.x, bv.x); o2.y = fmaf(av.y, v2.y, bv.y);
            o2.z = fmaf(av.z, v2.z, bv.z); o2.w = fmaf(av.w, v2.w, bv.w);
            o3.x = fmaf(av.x, v3.x, bv.x); o3.y = fmaf(av.y, v3.y, bv.y);
            o3.z = fmaf(av.z, v3.z, bv.z); o3.w = fmaf(av.w, v3.w, bv.w);
            const long long rstep = (long long)ROWSTEP * D;
            *(float4*)(q + 0 * rstep) = o0;
            *(float4*)(q + 1 * rstep) = o1;
            *(float4*)(q + 2 * rstep) = o2;
            *(float4*)(q + 3 * rstep) = o3;
        } else {
            for (int r = row0; r < ccpn; r += ROWSTEP) {
                float4 v = *(const float4*)(cb + r * TILE_D + l4);
                float4 o;
                o.x = fmaf(av.x, v.x, bv.x);
                o.y = fmaf(av.y, v.y, bv.y);
                o.z = fmaf(av.z, v.z, bv.z);
                o.w = fmaf(av.w, v.w, bv.w);
                *(float4*)(og + (long long)r * D + l4) = o;
            }
        }
        for (int r = ROW_TILE + row0; r < ccnt; r += ROWSTEP) {
            float4 v = *(const float4*)(cxg + (long long)r * D + l4);
            float4 o;
            o.x = fmaf(av.x, v.x, bv.x);
            o.y = fmaf(av.y, v.y, bv.y);
            o.z = fmaf(av.z, v.z, bv.z);
            o.w = fmaf(av.w, v.w, bv.w);
            *(float4*)(og + (long long)r * D + l4) = o;
        }
        __syncthreads();   // cb becomes prefetch target next iteration

        if (!has_next) break;
        t = tn;
        bsel ^= 1;
    }
}

extern "C" void kernel_launch(void* const* d_in, const int* in_sizes, int n_in,
                              void* d_out, int out_size)
{
    const float* x   = (const float*)d_in[0];
    const float* gnw = (const float*)d_in[1];
    const float* gnb = (const float*)d_in[2];
    const float* msc = (const float*)d_in[3];
    const int*   bn  = (const int*)d_in[4];
    float* out = (float*)d_out;

    const int D = in_sizes[1];     // HIDDEN
    const int B = in_sizes[4];     // NUM_GRAPHS

    cudaFuncSetAttribute(graphnorm_kernel,
                         cudaFuncAttributeMaxDynamicSharedMemorySize,
                         (int)SMEM_BYTES);

    int ntiles = B * (D / TILE_D);
    int grid = ntiles < NCTA ? ntiles : NCTA;
    graphnorm_kernel<<<grid, THREADS, SMEM_BYTES>>>(x, gnw, gnb, msc, bn, out, D, B);
}